// round 1
// baseline (speedup 1.0000x reference)
#include <cuda_runtime.h>
#include <math.h>

#define B_  32
#define S_  128
#define E_  512
#define H_  512
#define V_  32000
#define G3  1536   // 3*H

// Scratch (__device__ globals: no allocations allowed)
__device__ __align__(16) float g_xgates[S_ * B_ * G3];  // [s][b][g]
__device__ __align__(16) float g_hs[B_ * S_ * H_];      // [b][s][h]
__device__ __align__(16) float g_h[2][H_ * B_];         // [k][b] ping-pong

// ---------------------------------------------------------------------------
// init: hidden [1,B,H] -> g_h[0] laid out [k][b]
// ---------------------------------------------------------------------------
__global__ void init_h_kernel(const float* __restrict__ hidden) {
    int i = blockIdx.x * blockDim.x + threadIdx.x;
    if (i < B_ * H_) {
        int b = i / H_;
        int k = i % H_;
        g_h[0][k * B_ + b] = hidden[i];
    }
}

// ---------------------------------------------------------------------------
// GEMM C[m][n] = sum_k A[m][k] * B[n][k]   (both K-contiguous, row-major)
// MODE 0: gates     A=embed_x (ext), B=w_ih,  C=g_xgates (+bias, [s][b][g] remap)
// MODE 1: projection A=g_hs (int),   B=w_out, C=d_out    (row m = b*S+s direct)
// Tiles: 128x128 block, BK=8, 256 threads, 8x8 per thread.
// ---------------------------------------------------------------------------
template <int MODE>
__global__ void __launch_bounds__(256) gemm_nt_kernel(
    const float* __restrict__ A_ext,
    const float* __restrict__ Bm,
    const float* __restrict__ bias,
    float* __restrict__ C_ext,
    int N, int K)
{
    __shared__ float As[8][128];
    __shared__ float Bs[8][128];

    const float* A = (MODE == 0) ? A_ext : g_hs;
    float*       C = (MODE == 0) ? g_xgates : C_ext;

    const int t     = threadIdx.x;
    const int mBase = blockIdx.y * 128;
    const int nBase = blockIdx.x * 128;
    const int ty    = t >> 4;       // 0..15
    const int tx    = t & 15;       // 0..15
    const int lrow  = t >> 1;       // 0..127
    const int lq    = (t & 1) * 4;  // 0 or 4

    const float* Ab = A  + (size_t)(mBase + lrow) * K + lq;
    const float* Bb = Bm + (size_t)(nBase + lrow) * K + lq;

    float acc[8][8];
#pragma unroll
    for (int i = 0; i < 8; i++)
#pragma unroll
        for (int j = 0; j < 8; j++) acc[i][j] = 0.f;

    for (int k0 = 0; k0 < K; k0 += 8) {
        float4 av = *(const float4*)(Ab + k0);
        float4 bv = *(const float4*)(Bb + k0);
        __syncthreads();   // protect previous iteration's smem reads
        As[lq + 0][lrow] = av.x; As[lq + 1][lrow] = av.y;
        As[lq + 2][lrow] = av.z; As[lq + 3][lrow] = av.w;
        Bs[lq + 0][lrow] = bv.x; Bs[lq + 1][lrow] = bv.y;
        Bs[lq + 2][lrow] = bv.z; Bs[lq + 3][lrow] = bv.w;
        __syncthreads();

#pragma unroll
        for (int k = 0; k < 8; k++) {
            float ra[8], rb[8];
            *(float4*)(ra + 0) = *(const float4*)&As[k][ty * 8 + 0];
            *(float4*)(ra + 4) = *(const float4*)&As[k][ty * 8 + 4];
            *(float4*)(rb + 0) = *(const float4*)&Bs[k][tx * 8 + 0];
            *(float4*)(rb + 4) = *(const float4*)&Bs[k][tx * 8 + 4];
#pragma unroll
            for (int i = 0; i < 8; i++)
#pragma unroll
                for (int j = 0; j < 8; j++)
                    acc[i][j] += ra[i] * rb[j];
        }
    }

    // epilogue
#pragma unroll
    for (int i = 0; i < 8; i++) {
        int m  = mBase + ty * 8 + i;
        int n0 = nBase + tx * 8;
        if (MODE == 0) {
            // A row m corresponds to (b = m/S, s = m%S); write [s][b][g] + bias
            int s = m & (S_ - 1);
            int b = m >> 7;
            float* Crow = C + (size_t)(s * B_ + b) * G3 + n0;
            float4 v0, v1;
            v0.x = acc[i][0] + bias[n0 + 0]; v0.y = acc[i][1] + bias[n0 + 1];
            v0.z = acc[i][2] + bias[n0 + 2]; v0.w = acc[i][3] + bias[n0 + 3];
            v1.x = acc[i][4] + bias[n0 + 4]; v1.y = acc[i][5] + bias[n0 + 5];
            v1.z = acc[i][6] + bias[n0 + 6]; v1.w = acc[i][7] + bias[n0 + 7];
            *(float4*)(Crow + 0) = v0;
            *(float4*)(Crow + 4) = v1;
        } else {
            float* Crow = C + (size_t)m * N + n0;
            float4 v0, v1;
            v0.x = acc[i][0]; v0.y = acc[i][1]; v0.z = acc[i][2]; v0.w = acc[i][3];
            v1.x = acc[i][4]; v1.y = acc[i][5]; v1.z = acc[i][6]; v1.w = acc[i][7];
            *(float4*)(Crow + 0) = v0;
            *(float4*)(Crow + 4) = v1;
        }
    }
}

// ---------------------------------------------------------------------------
// One GRU step. grid = 128 blocks (4 h-columns each), 512 threads.
// Thread layout for dots: b = t&31, ks = (t>>5)&3 (K split of 128), jl = t>>7.
// Dyn smem: h staged [k*32+b] (64KB) + reduction buffer (6KB).
// ---------------------------------------------------------------------------
__global__ void __launch_bounds__(512) gru_step_kernel(
    const float* __restrict__ w_hh,
    const float* __restrict__ b_hh,
    int s)
{
    extern __shared__ float sm[];
    float* sh  = sm;              // [k*32 + b], 512*32 floats
    float* red = sm + H_ * B_;    // [gate][jl][ks][b] : ((g*4+jl)*4+ks)*32+b

    const int p = s & 1;
    const float* __restrict__ hcur = g_h[p];
    const int t = threadIdx.x;

    // stage h into smem (straight coalesced float4 copy)
    {
        const float4* src = (const float4*)hcur;
        float4*       dst = (float4*)sh;
#pragma unroll
        for (int i = t; i < (H_ * B_) / 4; i += 512) dst[i] = src[i];
    }
    __syncthreads();

    const int b  = t & 31;
    const int ks = (t >> 5) & 3;
    const int jl = t >> 7;
    const int jg = blockIdx.x * 4 + jl;

    const float4* wr = (const float4*)(w_hh + (size_t)(jg)          * H_ + ks * 128);
    const float4* wz = (const float4*)(w_hh + (size_t)(H_ + jg)     * H_ + ks * 128);
    const float4* wn = (const float4*)(w_hh + (size_t)(2 * H_ + jg) * H_ + ks * 128);
    const float* shp = sh + ks * 128 * B_ + b;

    float ar = 0.f, az = 0.f, an = 0.f;
#pragma unroll 8
    for (int kk = 0; kk < 32; kk++) {
        float4 r4 = wr[kk];
        float4 z4 = wz[kk];
        float4 n4 = wn[kk];
        float h0 = shp[(kk * 4 + 0) * B_];
        float h1 = shp[(kk * 4 + 1) * B_];
        float h2 = shp[(kk * 4 + 2) * B_];
        float h3 = shp[(kk * 4 + 3) * B_];
        ar += h0 * r4.x; ar += h1 * r4.y; ar += h2 * r4.z; ar += h3 * r4.w;
        az += h0 * z4.x; az += h1 * z4.y; az += h2 * z4.z; az += h3 * z4.w;
        an += h0 * n4.x; an += h1 * n4.y; an += h2 * n4.z; an += h3 * n4.w;
    }
    red[((0 * 4 + jl) * 4 + ks) * 32 + b] = ar;
    red[((1 * 4 + jl) * 4 + ks) * 32 + b] = az;
    red[((2 * 4 + jl) * 4 + ks) * 32 + b] = an;
    __syncthreads();

    if (t < 128) {
        const int b2  = t & 31;
        const int jl2 = t >> 5;
        const int jg2 = blockIdx.x * 4 + jl2;

        float sr = 0.f, sz = 0.f, sn = 0.f;
#pragma unroll
        for (int k2 = 0; k2 < 4; k2++) {
            sr += red[((0 * 4 + jl2) * 4 + k2) * 32 + b2];
            sz += red[((1 * 4 + jl2) * 4 + k2) * 32 + b2];
            sn += red[((2 * 4 + jl2) * 4 + k2) * 32 + b2];
        }
        const float* xg = g_xgates + (size_t)(s * B_ + b2) * G3;
        float hr = sr + b_hh[jg2];
        float hz = sz + b_hh[H_ + jg2];
        float hn = sn + b_hh[2 * H_ + jg2];
        float r = 1.f / (1.f + expf(-(xg[jg2] + hr)));
        float z = 1.f / (1.f + expf(-(xg[H_ + jg2] + hz)));
        float n = tanhf(xg[2 * H_ + jg2] + r * hn);
        float hold = sh[jg2 * B_ + b2];
        float hnew = (1.f - z) * n + z * hold;
        g_h[p ^ 1][jg2 * B_ + b2] = hnew;
        g_hs[((size_t)b2 * S_ + s) * H_ + jg2] = hnew;
    }
}

// ---------------------------------------------------------------------------
extern "C" void kernel_launch(void* const* d_in, const int* in_sizes, int n_in,
                              void* d_out, int out_size)
{
    const float* embed_x = (const float*)d_in[0];
    const float* hidden  = (const float*)d_in[1];
    const float* w_ih    = (const float*)d_in[2];
    const float* w_hh    = (const float*)d_in[3];
    const float* b_ih    = (const float*)d_in[4];
    const float* b_hh    = (const float*)d_in[5];
    const float* w_out   = (const float*)d_in[6];
    float* out = (float*)d_out;

    (void)in_sizes; (void)n_in; (void)out_size;

    // 70KB dynamic smem for the step kernel (idempotent, capture-safe)
    cudaFuncSetAttribute(gru_step_kernel,
                         cudaFuncAttributeMaxDynamicSharedMemorySize,
                         (H_ * B_ + G3) * (int)sizeof(float));

    // 1) init hidden state
    init_h_kernel<<<(B_ * H_ + 255) / 256, 256>>>(hidden);

    // 2) input-gate GEMM: x_gates = embed_x @ w_ih^T + b_ih
    {
        dim3 grid(G3 / 128, (B_ * S_) / 128);   // (12, 32)
        gemm_nt_kernel<0><<<grid, 256>>>(embed_x, w_ih, b_ih, nullptr, G3, E_);
    }

    // 3) sequential GRU scan
    const int smem_bytes = (H_ * B_ + G3) * (int)sizeof(float);
    for (int s = 0; s < S_; s++) {
        gru_step_kernel<<<H_ / 4, 512, smem_bytes>>>(w_hh, b_hh, s);
    }

    // 4) vocab projection: logits = hs @ w_out^T
    {
        dim3 grid(V_ / 128, (B_ * S_) / 128);   // (250, 32)
        gemm_nt_kernel<1><<<grid, 256>>>(nullptr, w_out, nullptr, out, V_, H_);
    }
}

// round 3
// speedup vs baseline: 1.2035x; 1.2035x over previous
#include <cuda_runtime.h>
#include <math.h>

#define B_  32
#define S_  128
#define E_  512
#define H_  512
#define V_  32000
#define G3  1536   // 3*H

// Scratch (__device__ globals: no allocations allowed)
__device__ __align__(16) float g_xgates[S_ * G3 * B_];  // [s][g][b]
__device__ __align__(16) float g_hs[B_ * S_ * H_];      // [b][s][h]
__device__ __align__(16) float g_h[2][B_ * H_];         // [b][k] ping-pong
__device__ unsigned long long g_bar = 0ULL;             // monotonic barrier ticket

// ---------------------------------------------------------------------------
// GEMM C[m][n] = sum_k A[m][k] * B[n][k]   (both K-contiguous, row-major)
// MODE 0: gates      A=embed_x (ext), B=w_ih,  C=g_xgates (+bias, [s][g][b])
// MODE 1: projection A=g_hs (int),    B=w_out, C=d_out    (row m = b*S+s)
// Tiles: 128x128 block, BK=8, 256 threads, 8x8 per thread.
// ---------------------------------------------------------------------------
template <int MODE>
__global__ void __launch_bounds__(256) gemm_nt_kernel(
    const float* __restrict__ A_ext,
    const float* __restrict__ Bm,
    const float* __restrict__ bias,
    float* __restrict__ C_ext,
    int N, int K)
{
    __shared__ float As[8][128];
    __shared__ float Bs[8][128];

    const float* A = (MODE == 0) ? A_ext : g_hs;
    float*       C = (MODE == 0) ? g_xgates : C_ext;

    const int t     = threadIdx.x;
    const int mBase = blockIdx.y * 128;
    const int nBase = blockIdx.x * 128;
    const int ty    = t >> 4;       // 0..15
    const int tx    = t & 15;       // 0..15
    const int lrow  = t >> 1;       // 0..127
    const int lq    = (t & 1) * 4;  // 0 or 4

    const float* Ab = A  + (size_t)(mBase + lrow) * K + lq;
    const float* Bb = Bm + (size_t)(nBase + lrow) * K + lq;

    float acc[8][8];
#pragma unroll
    for (int i = 0; i < 8; i++)
#pragma unroll
        for (int j = 0; j < 8; j++) acc[i][j] = 0.f;

    for (int k0 = 0; k0 < K; k0 += 8) {
        float4 av = *(const float4*)(Ab + k0);
        float4 bv = *(const float4*)(Bb + k0);
        __syncthreads();   // protect previous iteration's smem reads
        As[lq + 0][lrow] = av.x; As[lq + 1][lrow] = av.y;
        As[lq + 2][lrow] = av.z; As[lq + 3][lrow] = av.w;
        Bs[lq + 0][lrow] = bv.x; Bs[lq + 1][lrow] = bv.y;
        Bs[lq + 2][lrow] = bv.z; Bs[lq + 3][lrow] = bv.w;
        __syncthreads();

#pragma unroll
        for (int k = 0; k < 8; k++) {
            float ra[8], rb[8];
            *(float4*)(ra + 0) = *(const float4*)&As[k][ty * 8 + 0];
            *(float4*)(ra + 4) = *(const float4*)&As[k][ty * 8 + 4];
            *(float4*)(rb + 0) = *(const float4*)&Bs[k][tx * 8 + 0];
            *(float4*)(rb + 4) = *(const float4*)&Bs[k][tx * 8 + 4];
#pragma unroll
            for (int i = 0; i < 8; i++)
#pragma unroll
                for (int j = 0; j < 8; j++)
                    acc[i][j] += ra[i] * rb[j];
        }
    }

    // epilogue
#pragma unroll
    for (int i = 0; i < 8; i++) {
        int m  = mBase + ty * 8 + i;
        int n0 = nBase + tx * 8;
        if (MODE == 0) {
            // row m -> (b = m>>7, s = m&127); write [s][g][b] + bias
            int s = m & (S_ - 1);
            int b = m >> 7;
            float* Cb = C + (size_t)s * G3 * B_ + b;
#pragma unroll
            for (int j = 0; j < 8; j++)
                Cb[(size_t)(n0 + j) * B_] = acc[i][j] + bias[n0 + j];
        } else {
            float* Crow = C + (size_t)m * N + n0;
            float4 v0, v1;
            v0.x = acc[i][0]; v0.y = acc[i][1]; v0.z = acc[i][2]; v0.w = acc[i][3];
            v1.x = acc[i][4]; v1.y = acc[i][5]; v1.z = acc[i][6]; v1.w = acc[i][7];
            *(float4*)(Crow + 0) = v0;
            *(float4*)(Crow + 4) = v1;
        }
    }
}

// ---------------------------------------------------------------------------
// Persistent GRU scan. 128 blocks x 512 threads, all co-resident.
// Block j owns hidden columns 4j..4j+3 (x3 gates). w_hh slice staged in smem
// once; h exchanged through gmem [b][k] with a monotonic-ticket grid barrier.
// Barrier has a watchdog: if co-residency ever fails, we break out (test then
// reports wrong answer instead of hanging the container).
// ---------------------------------------------------------------------------
#define SH_PAD   4
#define SH_LDK   (H_ + SH_PAD)            // 516 floats per b row
#define WS_FLTS  (4 * 3 * H_)             // 6144
#define SH_FLTS  (B_ * SH_LDK)            // 16512
#define RED_FLTS (3 * 4 * 4 * B_)         // 1536
#define PERS_SMEM ((WS_FLTS + SH_FLTS + RED_FLTS) * (int)sizeof(float))

__device__ __forceinline__ void grid_barrier() {
    __syncthreads();
    if (threadIdx.x == 0) {
        __threadfence();
        unsigned long long ticket = atomicAdd(&g_bar, 1ULL);
        unsigned long long target = (ticket - (ticket & 127ULL)) + 128ULL;
        unsigned long long v;
        unsigned int guard = 0;
        do {
            asm volatile("ld.global.acquire.gpu.u64 %0, [%1];"
                         : "=l"(v) : "l"(&g_bar));
        } while (v < target && (++guard < (1u << 22)));
    }
    __syncthreads();
}

__global__ void __launch_bounds__(512) gru_scan_kernel(
    const float* __restrict__ hidden,
    const float* __restrict__ w_hh,
    const float* __restrict__ b_hh)
{
    extern __shared__ float sm[];
    float* ws  = sm;                        // [jl][g][k]  : (jl*3+g)*512 + k
    float* sh  = sm + WS_FLTS;              // [b][k+pad]  : b*516 + k
    float* red = sm + WS_FLTS + SH_FLTS;    // [g][jl][ks][b]

    float4*       ws4 = (float4*)ws;
    float4*       sh4 = (float4*)sh;        // b stride = 129 float4

    const int t   = threadIdx.x;
    const int blk = blockIdx.x;

    // --- one-time: stage w_hh slice (cols 4*blk..4*blk+3, 3 gates) ---
    {
        const float4* w4 = (const float4*)w_hh;
        for (int idx = t; idx < WS_FLTS / 4; idx += 512) {
            int jl  = idx / 384;          // 384 = 3*128
            int rem = idx - jl * 384;
            int g   = rem >> 7;
            int kq  = rem & 127;
            ws4[idx] = w4[(size_t)(g * H_ + blk * 4 + jl) * 128 + kq];
        }
    }

    // --- one-time: init g_h[0] = hidden (same [b][k] layout) ---
    {
        int idx = blk * 512 + t;
        if (idx < (B_ * H_) / 4)
            ((float4*)g_h[0])[idx] = ((const float4*)hidden)[idx];
    }
    grid_barrier();

    const int b  = t & 31;
    const int ks = (t >> 5) & 3;
    const int jl = t >> 7;

    // preload biases for finalize threads
    const int b2  = t & 31;
    const int jl2 = t >> 5;          // valid for t<128
    const int jg2 = blk * 4 + (jl2 & 3);
    float bhr = 0.f, bhz = 0.f, bhn = 0.f;
    if (t < 128) {
        bhr = b_hh[jg2];
        bhz = b_hh[H_ + jg2];
        bhn = b_hh[2 * H_ + jg2];
    }

    for (int s = 0; s < S_; s++) {
        const int p = s & 1;

        // stage h[p] (gmem [b][k]) -> smem [b][k+pad]
        {
            const float4* src = (const float4*)g_h[p];
            for (int i = t; i < (B_ * H_) / 4; i += 512) {
                int bb = i >> 7;
                int kq = i & 127;
                sh4[bb * (SH_LDK / 4) + kq] = src[i];
            }
        }
        __syncthreads();

        // dot products: thread (b, ks, jl) covers k in [ks*128, ks*128+128)
        float ar = 0.f, az = 0.f, an = 0.f;
        {
            const float4* hp = sh4 + b * (SH_LDK / 4) + ks * 32;
            const float4* wr = ws4 + (jl * 3 + 0) * 128 + ks * 32;
            const float4* wz = ws4 + (jl * 3 + 1) * 128 + ks * 32;
            const float4* wn = ws4 + (jl * 3 + 2) * 128 + ks * 32;
#pragma unroll
            for (int kk = 0; kk < 32; kk++) {
                float4 h4 = hp[kk];
                float4 r4 = wr[kk];
                float4 z4 = wz[kk];
                float4 n4 = wn[kk];
                ar += h4.x * r4.x; ar += h4.y * r4.y; ar += h4.z * r4.z; ar += h4.w * r4.w;
                az += h4.x * z4.x; az += h4.y * z4.y; az += h4.z * z4.z; az += h4.w * z4.w;
                an += h4.x * n4.x; an += h4.y * n4.y; an += h4.z * n4.z; an += h4.w * n4.w;
            }
        }
        red[((0 * 4 + jl) * 4 + ks) * 32 + b] = ar;
        red[((1 * 4 + jl) * 4 + ks) * 32 + b] = az;
        red[((2 * 4 + jl) * 4 + ks) * 32 + b] = an;
        __syncthreads();

        if (t < 128) {
            float sr = 0.f, sz = 0.f, sn = 0.f;
#pragma unroll
            for (int k2 = 0; k2 < 4; k2++) {
                sr += red[((0 * 4 + jl2) * 4 + k2) * 32 + b2];
                sz += red[((1 * 4 + jl2) * 4 + k2) * 32 + b2];
                sn += red[((2 * 4 + jl2) * 4 + k2) * 32 + b2];
            }
            // coalesced gate reads: g_xgates [s][g][b]
            const float* xg = g_xgates + (size_t)s * G3 * B_;
            float xr = xg[(size_t)(jg2)           * B_ + b2];
            float xz = xg[(size_t)(H_ + jg2)      * B_ + b2];
            float xn = xg[(size_t)(2 * H_ + jg2)  * B_ + b2];

            float r = 1.f / (1.f + expf(-(xr + sr + bhr)));
            float z = 1.f / (1.f + expf(-(xz + sz + bhz)));
            float n = tanhf(xn + r * (sn + bhn));
            float hold = sh[b2 * SH_LDK + jg2];
            float hnew = (1.f - z) * n + z * hold;

            g_h[p ^ 1][b2 * H_ + jg2] = hnew;
            g_hs[((size_t)b2 * S_ + s) * H_ + jg2] = hnew;
        }

        if (s < S_ - 1) grid_barrier();
        else __syncthreads();
    }
}

// ---------------------------------------------------------------------------
extern "C" void kernel_launch(void* const* d_in, const int* in_sizes, int n_in,
                              void* d_out, int out_size)
{
    const float* embed_x = (const float*)d_in[0];
    const float* hidden  = (const float*)d_in[1];
    const float* w_ih    = (const float*)d_in[2];
    const float* w_hh    = (const float*)d_in[3];
    const float* b_ih    = (const float*)d_in[4];
    const float* b_hh    = (const float*)d_in[5];
    const float* w_out   = (const float*)d_in[6];
    float* out = (float*)d_out;

    (void)in_sizes; (void)n_in; (void)out_size;

    cudaFuncSetAttribute(gru_scan_kernel,
                         cudaFuncAttributeMaxDynamicSharedMemorySize,
                         PERS_SMEM);

    // 1) input-gate GEMM: x_gates = embed_x @ w_ih^T + b_ih  -> [s][g][b]
    {
        dim3 grid(G3 / 128, (B_ * S_) / 128);   // (12, 32)
        gemm_nt_kernel<0><<<grid, 256>>>(embed_x, w_ih, b_ih, nullptr, G3, E_);
    }

    // 2) persistent GRU scan (single launch, grid barrier per step)
    gru_scan_kernel<<<H_ / 4, 512, PERS_SMEM>>>(hidden, w_hh, b_hh);

    // 3) vocab projection: logits = hs @ w_out^T
    {
        dim3 grid(V_ / 128, (B_ * S_) / 128);   // (250, 32)
        gemm_nt_kernel<1><<<grid, 256>>>(nullptr, w_out, nullptr, out, V_, H_);
    }
}

// round 5
// speedup vs baseline: 2.0912x; 1.7376x over previous
#include <cuda_runtime.h>
#include <cuda_bf16.h>
#include <math.h>
#include <stdint.h>

#define B_  32
#define S_  128
#define E_  512
#define H_  512
#define V_  32000
#define G3  1536   // 3*H

// ---------------------------------------------------------------------------
// Scratch (__device__ globals: no allocations allowed)
// ---------------------------------------------------------------------------
__device__ __align__(16) float g_xgates[S_ * G3 * B_];            // [s][g][b]
__device__ __align__(16) __nv_bfloat16 g_hs_hi[B_ * S_ * H_];     // [b][s][h] -> row m=b*S+s
__device__ __align__(16) __nv_bfloat16 g_hs_lo[B_ * S_ * H_];
__device__ __align__(16) __nv_bfloat16 g_wout_hi[(size_t)V_ * H_];
__device__ __align__(16) __nv_bfloat16 g_wout_lo[(size_t)V_ * H_];
__device__ __align__(16) float g_h[2][B_ * H_];                   // [b][k]
__device__ unsigned long long g_bar = 0ULL;

// ---------------------------------------------------------------------------
// w_out fp32 -> bf16 hi/lo split
// ---------------------------------------------------------------------------
__global__ void __launch_bounds__(256) convert_wout_kernel(const float* __restrict__ w) {
    size_t i = (size_t)blockIdx.x * 256 + threadIdx.x;      // float4 index
    const float4* w4 = (const float4*)w;
    float4 v = w4[i];
    __nv_bfloat16 h0 = __float2bfloat16(v.x);
    __nv_bfloat16 h1 = __float2bfloat16(v.y);
    __nv_bfloat16 h2 = __float2bfloat16(v.z);
    __nv_bfloat16 h3 = __float2bfloat16(v.w);
    __nv_bfloat16 l0 = __float2bfloat16(v.x - __bfloat162float(h0));
    __nv_bfloat16 l1 = __float2bfloat16(v.y - __bfloat162float(h1));
    __nv_bfloat16 l2 = __float2bfloat16(v.z - __bfloat162float(h2));
    __nv_bfloat16 l3 = __float2bfloat16(v.w - __bfloat162float(h3));
    ((__nv_bfloat162*)g_wout_hi)[i * 2 + 0] = __nv_bfloat162(h0, h1);
    ((__nv_bfloat162*)g_wout_hi)[i * 2 + 1] = __nv_bfloat162(h2, h3);
    ((__nv_bfloat162*)g_wout_lo)[i * 2 + 0] = __nv_bfloat162(l0, l1);
    ((__nv_bfloat162*)g_wout_lo)[i * 2 + 1] = __nv_bfloat162(l2, l3);
}

// ---------------------------------------------------------------------------
// Gates GEMM: x_gates[s][g][b] = embed_x @ w_ih^T + b_ih (unchanged from R3)
// ---------------------------------------------------------------------------
__global__ void __launch_bounds__(256) gemm_gates_kernel(
    const float* __restrict__ A,
    const float* __restrict__ Bm,
    const float* __restrict__ bias)
{
    __shared__ float As[8][128];
    __shared__ float Bs[8][128];

    const int t     = threadIdx.x;
    const int mBase = blockIdx.y * 128;
    const int nBase = blockIdx.x * 128;
    const int ty    = t >> 4;
    const int tx    = t & 15;
    const int lrow  = t >> 1;
    const int lq    = (t & 1) * 4;

    const float* Ab = A  + (size_t)(mBase + lrow) * E_ + lq;
    const float* Bb = Bm + (size_t)(nBase + lrow) * E_ + lq;

    float acc[8][8];
#pragma unroll
    for (int i = 0; i < 8; i++)
#pragma unroll
        for (int j = 0; j < 8; j++) acc[i][j] = 0.f;

    for (int k0 = 0; k0 < E_; k0 += 8) {
        float4 av = *(const float4*)(Ab + k0);
        float4 bv = *(const float4*)(Bb + k0);
        __syncthreads();
        As[lq + 0][lrow] = av.x; As[lq + 1][lrow] = av.y;
        As[lq + 2][lrow] = av.z; As[lq + 3][lrow] = av.w;
        Bs[lq + 0][lrow] = bv.x; Bs[lq + 1][lrow] = bv.y;
        Bs[lq + 2][lrow] = bv.z; Bs[lq + 3][lrow] = bv.w;
        __syncthreads();

#pragma unroll
        for (int k = 0; k < 8; k++) {
            float ra[8], rb[8];
            *(float4*)(ra + 0) = *(const float4*)&As[k][ty * 8 + 0];
            *(float4*)(ra + 4) = *(const float4*)&As[k][ty * 8 + 4];
            *(float4*)(rb + 0) = *(const float4*)&Bs[k][tx * 8 + 0];
            *(float4*)(rb + 4) = *(const float4*)&Bs[k][tx * 8 + 4];
#pragma unroll
            for (int i = 0; i < 8; i++)
#pragma unroll
                for (int j = 0; j < 8; j++)
                    acc[i][j] += ra[i] * rb[j];
        }
    }

#pragma unroll
    for (int i = 0; i < 8; i++) {
        int m  = mBase + ty * 8 + i;
        int n0 = nBase + tx * 8;
        int s = m & (S_ - 1);
        int b = m >> 7;
        float* Cb = g_xgates + (size_t)s * G3 * B_ + b;
#pragma unroll
        for (int j = 0; j < 8; j++)
            Cb[(size_t)(n0 + j) * B_] = acc[i][j] + bias[n0 + j];
    }
}

// ---------------------------------------------------------------------------
// Persistent GRU scan (emits hs as bf16 hi/lo); unchanged from R3/R4
// ---------------------------------------------------------------------------
#define SH_PAD   4
#define SH_LDK   (H_ + SH_PAD)
#define WS_FLTS  (4 * 3 * H_)
#define SH_FLTS  (B_ * SH_LDK)
#define RED_FLTS (3 * 4 * 4 * B_)
#define PERS_SMEM ((WS_FLTS + SH_FLTS + RED_FLTS) * (int)sizeof(float))

__device__ __forceinline__ void grid_barrier() {
    __syncthreads();
    if (threadIdx.x == 0) {
        __threadfence();
        unsigned long long ticket = atomicAdd(&g_bar, 1ULL);
        unsigned long long target = (ticket - (ticket & 127ULL)) + 128ULL;
        unsigned long long v;
        unsigned int guard = 0;
        do {
            asm volatile("ld.global.acquire.gpu.u64 %0, [%1];"
                         : "=l"(v) : "l"(&g_bar));
        } while (v < target && (++guard < (1u << 22)));
    }
    __syncthreads();
}

__global__ void __launch_bounds__(512) gru_scan_kernel(
    const float* __restrict__ hidden,
    const float* __restrict__ w_hh,
    const float* __restrict__ b_hh)
{
    extern __shared__ float sm[];
    float* ws  = sm;
    float* sh  = sm + WS_FLTS;
    float* red = sm + WS_FLTS + SH_FLTS;

    float4* ws4 = (float4*)ws;
    float4* sh4 = (float4*)sh;

    const int t   = threadIdx.x;
    const int blk = blockIdx.x;

    {
        const float4* w4 = (const float4*)w_hh;
        for (int idx = t; idx < WS_FLTS / 4; idx += 512) {
            int jl  = idx / 384;
            int rem = idx - jl * 384;
            int g   = rem >> 7;
            int kq  = rem & 127;
            ws4[idx] = w4[(size_t)(g * H_ + blk * 4 + jl) * 128 + kq];
        }
    }
    {
        int idx = blk * 512 + t;
        if (idx < (B_ * H_) / 4)
            ((float4*)g_h[0])[idx] = ((const float4*)hidden)[idx];
    }
    grid_barrier();

    const int b  = t & 31;
    const int ks = (t >> 5) & 3;
    const int jl = t >> 7;

    const int b2  = t & 31;
    const int jl2 = t >> 5;
    const int jg2 = blk * 4 + (jl2 & 3);
    float bhr = 0.f, bhz = 0.f, bhn = 0.f;
    if (t < 128) {
        bhr = b_hh[jg2];
        bhz = b_hh[H_ + jg2];
        bhn = b_hh[2 * H_ + jg2];
    }

    for (int s = 0; s < S_; s++) {
        const int p = s & 1;
        {
            const float4* src = (const float4*)g_h[p];
            for (int i = t; i < (B_ * H_) / 4; i += 512) {
                int bb = i >> 7;
                int kq = i & 127;
                sh4[bb * (SH_LDK / 4) + kq] = src[i];
            }
        }
        __syncthreads();

        float ar = 0.f, az = 0.f, an = 0.f;
        {
            const float4* hp = sh4 + b * (SH_LDK / 4) + ks * 32;
            const float4* wr = ws4 + (jl * 3 + 0) * 128 + ks * 32;
            const float4* wz = ws4 + (jl * 3 + 1) * 128 + ks * 32;
            const float4* wn = ws4 + (jl * 3 + 2) * 128 + ks * 32;
#pragma unroll
            for (int kk = 0; kk < 32; kk++) {
                float4 h4 = hp[kk];
                float4 r4 = wr[kk];
                float4 z4 = wz[kk];
                float4 n4 = wn[kk];
                ar += h4.x * r4.x; ar += h4.y * r4.y; ar += h4.z * r4.z; ar += h4.w * r4.w;
                az += h4.x * z4.x; az += h4.y * z4.y; az += h4.z * z4.z; az += h4.w * z4.w;
                an += h4.x * n4.x; an += h4.y * n4.y; an += h4.z * n4.z; an += h4.w * n4.w;
            }
        }
        red[((0 * 4 + jl) * 4 + ks) * 32 + b] = ar;
        red[((1 * 4 + jl) * 4 + ks) * 32 + b] = az;
        red[((2 * 4 + jl) * 4 + ks) * 32 + b] = an;
        __syncthreads();

        if (t < 128) {
            float sr = 0.f, sz = 0.f, sn = 0.f;
#pragma unroll
            for (int k2 = 0; k2 < 4; k2++) {
                sr += red[((0 * 4 + jl2) * 4 + k2) * 32 + b2];
                sz += red[((1 * 4 + jl2) * 4 + k2) * 32 + b2];
                sn += red[((2 * 4 + jl2) * 4 + k2) * 32 + b2];
            }
            const float* xg = g_xgates + (size_t)s * G3 * B_;
            float xr = xg[(size_t)(jg2)          * B_ + b2];
            float xz = xg[(size_t)(H_ + jg2)     * B_ + b2];
            float xn = xg[(size_t)(2 * H_ + jg2) * B_ + b2];

            float r = 1.f / (1.f + expf(-(xr + sr + bhr)));
            float z = 1.f / (1.f + expf(-(xz + sz + bhz)));
            float n = tanhf(xn + r * (sn + bhn));
            float hold = sh[b2 * SH_LDK + jg2];
            float hnew = (1.f - z) * n + z * hold;

            g_h[p ^ 1][b2 * H_ + jg2] = hnew;

            size_t oi = ((size_t)b2 * S_ + s) * H_ + jg2;
            __nv_bfloat16 hi = __float2bfloat16(hnew);
            g_hs_hi[oi] = hi;
            g_hs_lo[oi] = __float2bfloat16(hnew - __bfloat162float(hi));
        }

        if (s < S_ - 1) grid_barrier();
        else __syncthreads();
    }
}

// ---------------------------------------------------------------------------
// Projection via warp-level mma.sync (HMMA bf16, fp32 accum), 3-term split.
// 128x128 tile/CTA, 8 warps (2x4 of 64x32), BK=32, cp.async double buffer.
// Smem tile: 128 rows x 32 bf16, pitch 40 bf16 (80B, conflict-free ldmatrix).
// ---------------------------------------------------------------------------
#define PROJ_PITCH_B 80                       // bytes per smem row
#define PROJ_TILE_B  (128 * PROJ_PITCH_B)     // 10240
#define PROJ_BUF_B   (4 * PROJ_TILE_B)        // 40960 (Ah, Al, Bh, Bl)
#define PROJ_SMEM    (2 * PROJ_BUF_B)         // 81920
#define KCH 16                                // 512 / 32

__device__ __forceinline__ uint32_t smem_u32(const void* p) {
    uint32_t a;
    asm("{ .reg .u64 tmp; cvta.to.shared.u64 tmp, %1; cvt.u32.u64 %0, tmp; }"
        : "=r"(a) : "l"(p));
    return a;
}
__device__ __forceinline__ void cp_async16(uint32_t saddr, const void* gaddr) {
    asm volatile("cp.async.cg.shared.global [%0], [%1], 16;" :: "r"(saddr), "l"(gaddr));
}
__device__ __forceinline__ void ldm_x4(uint32_t* r, uint32_t addr) {
    asm volatile("ldmatrix.sync.aligned.m8n8.x4.shared.b16 {%0,%1,%2,%3}, [%4];"
                 : "=r"(r[0]), "=r"(r[1]), "=r"(r[2]), "=r"(r[3]) : "r"(addr));
}
__device__ __forceinline__ void ldm_x2(uint32_t* r, uint32_t addr) {
    asm volatile("ldmatrix.sync.aligned.m8n8.x2.shared.b16 {%0,%1}, [%2];"
                 : "=r"(r[0]), "=r"(r[1]) : "r"(addr));
}
__device__ __forceinline__ void mma16816(float* c, const uint32_t* a, const uint32_t* b) {
    asm volatile(
        "mma.sync.aligned.m16n8k16.row.col.f32.bf16.bf16.f32 "
        "{%0,%1,%2,%3}, {%4,%5,%6,%7}, {%8,%9}, {%0,%1,%2,%3};"
        : "+f"(c[0]), "+f"(c[1]), "+f"(c[2]), "+f"(c[3])
        : "r"(a[0]), "r"(a[1]), "r"(a[2]), "r"(a[3]), "r"(b[0]), "r"(b[1]));
}

__device__ __forceinline__ void proj_prefetch(
    uint32_t sbase, int buf, int kc, int mBase, int nBase, int t)
{
    const __nv_bfloat16* srcA_hi = g_hs_hi;
    const __nv_bfloat16* srcA_lo = g_hs_lo;
    const __nv_bfloat16* srcB_hi = g_wout_hi;
    const __nv_bfloat16* srcB_lo = g_wout_lo;
    uint32_t bb = sbase + (uint32_t)buf * PROJ_BUF_B;
#pragma unroll
    for (int i = 0; i < 2; i++) {
        int idx = t + i * 256;           // 0..511
        int row = idx >> 2;
        int q   = idx & 3;
        size_t gA = (size_t)(mBase + row) * H_ + kc * 32 + q * 8;
        size_t gB = (size_t)(nBase + row) * H_ + kc * 32 + q * 8;
        uint32_t so = (uint32_t)(row * PROJ_PITCH_B + q * 16);
        cp_async16(bb + 0 * PROJ_TILE_B + so, srcA_hi + gA);
        cp_async16(bb + 1 * PROJ_TILE_B + so, srcA_lo + gA);
        cp_async16(bb + 2 * PROJ_TILE_B + so, srcB_hi + gB);
        cp_async16(bb + 3 * PROJ_TILE_B + so, srcB_lo + gB);
    }
}

__global__ void __launch_bounds__(256, 1) proj_mma_kernel(float* __restrict__ out)
{
    extern __shared__ __align__(128) char smem[];
    const uint32_t sbase = smem_u32(smem);

    const int t    = threadIdx.x;
    const int wid  = t >> 5;
    const int lane = t & 31;
    const int wm   = wid >> 2;          // 0..1
    const int wn   = wid & 3;           // 0..3
    const int mBase = blockIdx.x * 128; // fast dim (B-tile L2 reuse)
    const int nBase = blockIdx.y * 128;

    float acc[4][4][4];
#pragma unroll
    for (int i = 0; i < 4; i++)
#pragma unroll
        for (int j = 0; j < 4; j++)
#pragma unroll
            for (int q = 0; q < 4; q++) acc[i][j][q] = 0.f;

    proj_prefetch(sbase, 0, 0, mBase, nBase, t);
    asm volatile("cp.async.commit_group;" ::: "memory");

    int buf = 0;
    for (int kc = 0; kc < KCH; kc++) {
        __syncthreads();    // everyone done reading buf^1 (prev compute)
        if (kc + 1 < KCH) {
            proj_prefetch(sbase, buf ^ 1, kc + 1, mBase, nBase, t);
            asm volatile("cp.async.commit_group;" ::: "memory");
            asm volatile("cp.async.wait_group 1;" ::: "memory");
        } else {
            asm volatile("cp.async.wait_group 0;" ::: "memory");
        }
        __syncthreads();    // chunk kc visible to all

        const uint32_t bb = sbase + (uint32_t)buf * PROJ_BUF_B;
#pragma unroll
        for (int ks = 0; ks < 2; ks++) {
            uint32_t aH[4][4], aL[4][4], bH[4][2], bL[4][2];
            const int kbA = ks * 32 + (lane >> 4) * 16;           // byte offset
            const int kbB = ks * 32 + ((lane >> 3) & 1) * 16;
#pragma unroll
            for (int mf = 0; mf < 4; mf++) {
                uint32_t ar = bb + (uint32_t)((wm * 64 + mf * 16 + (lane & 15)) * PROJ_PITCH_B + kbA);
                ldm_x4(aH[mf], ar);
                ldm_x4(aL[mf], ar + PROJ_TILE_B);
            }
#pragma unroll
            for (int nf = 0; nf < 4; nf++) {
                uint32_t br = bb + 2 * PROJ_TILE_B +
                              (uint32_t)((wn * 32 + nf * 8 + (lane & 7)) * PROJ_PITCH_B + kbB);
                ldm_x2(bH[nf], br);
                ldm_x2(bL[nf], br + PROJ_TILE_B);
            }
#pragma unroll
            for (int mf = 0; mf < 4; mf++)
#pragma unroll
                for (int nf = 0; nf < 4; nf++) {
                    mma16816(acc[mf][nf], aH[mf], bH[nf]);
                    mma16816(acc[mf][nf], aH[mf], bL[nf]);
                    mma16816(acc[mf][nf], aL[mf], bH[nf]);
                }
        }
        buf ^= 1;
    }

    // epilogue: c frag mapping (m16n8): row=(lane>>2)+{0,8}, col=(lane&3)*2+{0,1}
    const int r0 = lane >> 2;
    const int c0 = (lane & 3) * 2;
#pragma unroll
    for (int mf = 0; mf < 4; mf++) {
#pragma unroll
        for (int nf = 0; nf < 4; nf++) {
            int m = mBase + wm * 64 + mf * 16 + r0;
            int n = nBase + wn * 32 + nf * 8 + c0;
            float* p0 = out + (size_t)m * V_ + n;
            float* p1 = out + (size_t)(m + 8) * V_ + n;
            *(float2*)p0 = make_float2(acc[mf][nf][0], acc[mf][nf][1]);
            *(float2*)p1 = make_float2(acc[mf][nf][2], acc[mf][nf][3]);
        }
    }
}

// ---------------------------------------------------------------------------
extern "C" void kernel_launch(void* const* d_in, const int* in_sizes, int n_in,
                              void* d_out, int out_size)
{
    const float* embed_x = (const float*)d_in[0];
    const float* hidden  = (const float*)d_in[1];
    const float* w_ih    = (const float*)d_in[2];
    const float* w_hh    = (const float*)d_in[3];
    const float* b_ih    = (const float*)d_in[4];
    const float* b_hh    = (const float*)d_in[5];
    const float* w_out   = (const float*)d_in[6];
    float* out = (float*)d_out;

    (void)in_sizes; (void)n_in; (void)out_size;

    cudaFuncSetAttribute(gru_scan_kernel,
                         cudaFuncAttributeMaxDynamicSharedMemorySize, PERS_SMEM);
    cudaFuncSetAttribute(proj_mma_kernel,
                         cudaFuncAttributeMaxDynamicSharedMemorySize, PROJ_SMEM);

    // 1) convert w_out to bf16 hi/lo
    convert_wout_kernel<<<((size_t)V_ * H_ / 4) / 256, 256>>>(w_out);

    // 2) gates GEMM: x_gates = embed_x @ w_ih^T + b_ih  -> [s][g][b]
    {
        dim3 grid(G3 / 128, (B_ * S_) / 128);   // (12, 32)
        gemm_gates_kernel<<<grid, 256>>>(embed_x, w_ih, b_ih);
    }

    // 3) persistent GRU scan (emits hs as bf16 hi/lo)
    gru_scan_kernel<<<H_ / 4, 512, PERS_SMEM>>>(hidden, w_hh, b_hh);

    // 4) projection via HMMA bf16-split
    {
        dim3 grid((B_ * S_) / 128, V_ / 128);   // (32, 250)
        proj_mma_kernel<<<grid, 256, PROJ_SMEM>>>(out);
    }
}